// round 12
// baseline (speedup 1.0000x reference)
#include <cuda_runtime.h>
#include <math.h>
#include <stdint.h>

// Problem constants (GridPool, N=300000, B=4, C_IN=64, C_OUT=128, GRID=0.5)
#define NPTS   300000
#define CIN    64
#define COUT   128
#define NSCN   4
// voxel coords < 20 (coords in [0,10), grid 0.5); base-32 remap preserves
// lexicographic (b,vx,vy,vz) order, hence identical unique/rank ordering.
#define MDIM2  32
#define KSIZE  (NSCN*MDIM2*MDIM2*MDIM2)   // 131,072 keys
#define NWORDS (KSIZE/32)                 // 4,096 bitmap words
#define CSL    32768                      // cluster-rank bound: 4*20^3=32000 < 32768
#define GRIDSZ 0.5f
#define BN_EPS 1e-5f

// ---------------- scratch (device globals) -----------------------------------
__device__ float    g_x[(size_t)NPTS*COUT];     // fc output (fp32)
__device__ int      g_vkey[NPTS];
__device__ int      g_cluster[NPTS];
__device__ unsigned g_bits[NWORDS];             // presence bitmap (1 bit/key)
__device__ int      g_wordrank[NWORDS];         // exclusive popcount scan per word
__device__ int      g_ncl;                      // total cluster count
__device__ unsigned g_startbits[NSCN*3];        // per-scene min coord (float bits)
__device__ float    g_colstats[2*COUT];         // [0:128) sum, [128:256) sumsq
__device__ int      g_ccnt[CSL];                // per-cluster point count
__device__ int      g_cstart[CSL];              // per-cluster start (end after fill)
__device__ int      g_plist[NPTS];              // point indices grouped by cluster

// ---------------- packed f32x2 helpers ---------------------------------------
#define FMA_F32X2(acc, a2, b2) \
    asm("fma.rn.f32x2 %0, %1, %2, %0;" : "+l"(acc) : "l"(a2), "l"(b2))
#define PACK_DUP_F32X2(out, f) \
    asm("mov.b64 %0, {%1, %1};" : "=l"(out) : "f"(f))
#define UNPACK_F32X2(lo, hi, in) \
    asm("mov.b64 {%0, %1}, %2;" : "=f"(lo), "=f"(hi) : "l"(in))

// ---------------- helpers ----------------------------------------------------
__device__ __forceinline__ int point_batch(int i, int o0, int o1, int o2) {
    return (i >= o0) + (i >= o1) + (i >= o2);
}

__device__ unsigned block_exscan256u(unsigned v) {   // 256 threads
    unsigned lane = threadIdx.x & 31, wid = threadIdx.x >> 5;
    unsigned x = v;
    #pragma unroll
    for (int o = 1; o < 32; o <<= 1) {
        unsigned y = __shfl_up_sync(0xffffffffu, x, o);
        if (lane >= o) x += y;
    }
    __shared__ unsigned ws[8];
    if (lane == 31) ws[wid] = x;
    __syncthreads();
    unsigned woff = 0;
    #pragma unroll
    for (unsigned w = 0; w < 8; w++) woff += (w < wid) ? ws[w] : 0u;
    __syncthreads();
    return woff + x - v;
}

// ---------------- kernels ----------------------------------------------------
// per-scene min coordinate (grid-stride, coalesced). coords >= 0.
__global__ void k_scene_min(const float* __restrict__ coord,
                            const int* __restrict__ offset, int n) {
    __shared__ unsigned smin[NSCN*3];
    if (threadIdx.x < NSCN*3) smin[threadIdx.x] = 0xFFFFFFFFu;
    __syncthreads();
    int o0 = offset[0], o1 = offset[1], o2 = offset[2];
    for (int i = blockIdx.x*blockDim.x + threadIdx.x; i < n; i += gridDim.x*blockDim.x) {
        int b = point_batch(i, o0, o1, o2);
        #pragma unroll
        for (int d = 0; d < 3; d++)
            atomicMin(&smin[b*3+d], __float_as_uint(coord[(size_t)i*3+d]));
    }
    __syncthreads();
    if (threadIdx.x < NSCN*3) atomicMin(&g_startbits[threadIdx.x], smin[threadIdx.x]);
}

// voxel key per point + presence bit
__global__ void k_vkey(const float* __restrict__ coord,
                       const int* __restrict__ offset, int n) {
    int i = blockIdx.x*blockDim.x + threadIdx.x;
    if (i >= n) return;
    int o0 = offset[0], o1 = offset[1], o2 = offset[2];
    int b = point_batch(i, o0, o1, o2);
    float sx = __uint_as_float(g_startbits[b*3+0]);
    float sy = __uint_as_float(g_startbits[b*3+1]);
    float sz = __uint_as_float(g_startbits[b*3+2]);
    int vx = (int)floorf((coord[(size_t)i*3+0] - sx) / GRIDSZ);
    int vy = (int)floorf((coord[(size_t)i*3+1] - sy) / GRIDSZ);
    int vz = (int)floorf((coord[(size_t)i*3+2] - sz) / GRIDSZ);
    int key = ((b*MDIM2 + vx)*MDIM2 + vy)*MDIM2 + vz;
    g_vkey[i] = key;
    atomicOr(&g_bits[key >> 5], 1u << (key & 31));
}

// single-block bit scan: 256 threads x 16 words = 4096 words
__global__ void __launch_bounds__(256) b_scan() {
    int base = threadIdx.x*16;
    unsigned pc[16];
    const uint4* p = (const uint4*)&g_bits[base];
    unsigned s = 0;
    #pragma unroll
    for (int j = 0; j < 4; j++) {
        uint4 q = p[j];
        pc[j*4+0]=__popc(q.x); pc[j*4+1]=__popc(q.y);
        pc[j*4+2]=__popc(q.z); pc[j*4+3]=__popc(q.w);
        s += pc[j*4+0]+pc[j*4+1]+pc[j*4+2]+pc[j*4+3];
    }
    unsigned run = block_exscan256u(s);
    #pragma unroll
    for (int j = 0; j < 16; j++) { g_wordrank[base+j] = (int)run; run += pc[j]; }
    if (threadIdx.x == 255) g_ncl = (int)run;
}

// fp32 GEMM using packed fma.rn.f32x2 (FFMA2), fused column stats.
// Tile 128x128, 8 warps; thread covers rows 16i+ty, col pairs 32nt+2tx.
__global__ void __launch_bounds__(256)
k_gemm(const float* __restrict__ feat, const float* __restrict__ Wm, int n) {
    extern __shared__ float sm[];
    float* As = sm;                 // 128 x 65 (padded)
    float* Bs = sm + 128*65;        // 64 x 128 (k-major)
    int tid = threadIdx.x;
    int row0 = blockIdx.x*128;

    for (int t = tid; t < 128*64; t += 256) {
        int r = t >> 6, c = t & 63;
        int gr = row0 + r;
        As[r*65+c] = (gr < n) ? feat[(size_t)gr*CIN + c] : 0.f;
    }
    {
        float4* B4 = (float4*)Bs;
        const float4* W4 = (const float4*)Wm;
        for (int t = tid; t < (CIN*COUT)/4; t += 256) B4[t] = W4[t];
    }
    __syncthreads();

    int tx = tid & 15, ty = tid >> 4;
    unsigned long long acc2[8][4];
    #pragma unroll
    for (int i = 0; i < 8; i++)
        #pragma unroll
        for (int nt = 0; nt < 4; nt++) acc2[i][nt] = 0ull;

    #pragma unroll 8
    for (int k = 0; k < CIN; k++) {
        unsigned long long ra2[8], rb2[4];
        #pragma unroll
        for (int i = 0; i < 8; i++) {
            float a = As[(16*i+ty)*65 + k];
            PACK_DUP_F32X2(ra2[i], a);
        }
        #pragma unroll
        for (int nt = 0; nt < 4; nt++)
            rb2[nt] = *(const unsigned long long*)&Bs[k*COUT + 32*nt + 2*tx];
        #pragma unroll
        for (int i = 0; i < 8; i++)
            #pragma unroll
            for (int nt = 0; nt < 4; nt++)
                FMA_F32X2(acc2[i][nt], ra2[i], rb2[nt]);
    }

    // store x (float2 per col pair)
    #pragma unroll
    for (int i = 0; i < 8; i++) {
        int gr = row0 + 16*i + ty;
        if (gr < n) {
            #pragma unroll
            for (int nt = 0; nt < 4; nt++)
                *(unsigned long long*)&g_x[(size_t)gr*COUT + 32*nt + 2*tx] = acc2[i][nt];
        }
    }

    // fused column stats: rows beyond n contribute 0 (As zero-padded)
    __syncthreads();                // done reading As/Bs
    float* rsum = sm;               // 128 cols x 16 ty
    float* rsq  = sm + 2048;
    #pragma unroll
    for (int nt = 0; nt < 4; nt++) {
        float s0 = 0.f, s1 = 0.f, q0 = 0.f, q1 = 0.f;
        #pragma unroll
        for (int i = 0; i < 8; i++) {
            float lo, hi;
            UNPACK_F32X2(lo, hi, acc2[i][nt]);
            s0 += lo; s1 += hi;
            q0 += lo*lo; q1 += hi*hi;
        }
        int col = 32*nt + 2*tx;
        rsum[col*16 + ty]     = s0;
        rsum[(col+1)*16 + ty] = s1;
        rsq [col*16 + ty]     = q0;
        rsq [(col+1)*16 + ty] = q1;
    }
    __syncthreads();
    if (tid < COUT) {
        float s = 0.f, q = 0.f;
        #pragma unroll
        for (int t = 0; t < 16; t++) { s += rsum[tid*16+t]; q += rsq[tid*16+t]; }
        atomicAdd(&g_colstats[tid], s);
        atomicAdd(&g_colstats[COUT + tid], q);
    }
}

// cluster id per point (rank via bitmap popcount) + per-cluster counts
__global__ void k_assign(float* __restrict__ oClus, int n) {
    int i = blockIdx.x*blockDim.x + threadIdx.x;
    if (i >= n) return;
    int key = g_vkey[i];
    unsigned w = g_bits[key >> 5];
    int c = g_wordrank[key >> 5] + __popc(w & ((1u << (key & 31)) - 1u));
    g_cluster[i] = c;
    oClus[i] = (float)c;
    atomicAdd(&g_ccnt[c], 1);
}

// single-block count scan over CSL=32768 slots (two-pass, low regs)
__global__ void __launch_bounds__(256) c_scan() {
    int base = threadIdx.x*128;
    const int4* p = (const int4*)&g_ccnt[base];
    int s = 0;
    #pragma unroll
    for (int j = 0; j < 32; j++) { int4 v = p[j]; s += v.x+v.y+v.z+v.w; }
    int run = (int)block_exscan256u((unsigned)s);
    int4* q = (int4*)&g_cstart[base];
    #pragma unroll
    for (int j = 0; j < 32; j++) {
        int4 v = p[j];
        int4 o;
        o.x = run;  run += v.x;
        o.y = run;  run += v.y;
        o.z = run;  run += v.z;
        o.w = run;  run += v.w;
        q[j] = o;
    }
}

// fill point lists (mutates g_cstart -> segment end)
__global__ void k_fill(int n) {
    int i = blockIdx.x*blockDim.x + threadIdx.x;
    if (i >= n) return;
    int c = g_cluster[i];
    int slot = atomicAdd(&g_cstart[c], 1);
    g_plist[slot] = i;
}

// sentinel fill for batch_out (segment_min identity for empty segments)
__global__ void k_fillbatch(float* __restrict__ oBatch, int n) {
    int i = blockIdx.x*blockDim.x + threadIdx.x;
    if (i < n) oBatch[i] = 2147483648.0f;   // (float)INT32_MAX
}

// one block per REAL cluster: feature max, coord mean, count, batch.
__global__ void __launch_bounds__(128)
k_gather(const float* __restrict__ coord,
         const int* __restrict__ offset,
         const float* __restrict__ gamma,
         const float* __restrict__ beta,
         float* __restrict__ oCoord, float* __restrict__ oFeat,
         float* __restrict__ oCnt, float* __restrict__ oBatch, int n) {
    int j = threadIdx.x;            // 128 threads
    int ncl = g_ncl;
    float inv_n = 1.f / (float)n;
    float mean = g_colstats[j] * inv_n;
    float var  = g_colstats[COUT + j] * inv_n - mean*mean;
    float a    = gamma[j] * rsqrtf(var + BN_EPS);
    float bb   = beta[j] - a*mean;
    int o0 = offset[0], o1 = offset[1], o2 = offset[2];

    for (int c = blockIdx.x; c < ncl; c += gridDim.x) {
        int cnt = g_ccnt[c];
        int end = g_cstart[c];
        int start = end - cnt;
        float m0 = 0.f, m1 = 0.f;       // ReLU identity
        int p = 0;
        for (; p + 1 < cnt; p += 2) {
            int i0 = g_plist[start+p];
            int i1 = g_plist[start+p+1];
            float y0 = a * g_x[(size_t)i0*COUT + j] + bb;
            float y1 = a * g_x[(size_t)i1*COUT + j] + bb;
            m0 = fmaxf(m0, y0);
            m1 = fmaxf(m1, y1);
        }
        if (p < cnt) {
            int i0 = g_plist[start+p];
            m0 = fmaxf(m0, a * g_x[(size_t)i0*COUT + j] + bb);
        }
        oFeat[(size_t)c*COUT + j] = fmaxf(m0, m1);
        if (j < 3) {
            float s = 0.f;
            for (int q = 0; q < cnt; q++) {
                int i = g_plist[start+q];
                s += coord[(size_t)i*3 + j];
            }
            oCoord[(size_t)c*3 + j] = s / (float)cnt;
        }
        if (j == 0) {
            oCnt[c] = (float)cnt;
            int i0 = g_plist[start];
            oBatch[c] = (float)point_batch(i0, o0, o1, o2);
        }
    }
}

// ---------------- launch -----------------------------------------------------
extern "C" void kernel_launch(void* const* d_in, const int* in_sizes, int n_in,
                              void* d_out, int out_size) {
    const float* coord  = (const float*)d_in[0];
    const float* feat   = (const float*)d_in[1];
    const int*   offset = (const int*)  d_in[2];
    const float* Wm     = (const float*)d_in[3];
    const float* gamma  = (const float*)d_in[4];
    const float* beta   = (const float*)d_in[5];
    const int n = in_sizes[0] / 3;

    float* out    = (float*)d_out;
    float* oCoord = out;
    float* oFeat  = out + (size_t)3*n;
    float* oClus  = out + (size_t)131*n;
    float* oCnt   = out + (size_t)132*n;
    float* oBatch = out + (size_t)133*n;

    void *pBits, *pStart, *pStats, *pCcnt;
    cudaGetSymbolAddress(&pBits,  g_bits);
    cudaGetSymbolAddress(&pStart, g_startbits);
    cudaGetSymbolAddress(&pStats, g_colstats);
    cudaGetSymbolAddress(&pCcnt,  g_ccnt);

    static cudaStream_t s2 = nullptr, s3 = nullptr;
    static cudaEvent_t evRoot = nullptr, ev2 = nullptr, ev3 = nullptr;
    static bool init_done = false;
    if (!init_done) {
        cudaStreamCreateWithFlags(&s2, cudaStreamNonBlocking);
        cudaStreamCreateWithFlags(&s3, cudaStreamNonBlocking);
        cudaEventCreateWithFlags(&evRoot, cudaEventDisableTiming);
        cudaEventCreateWithFlags(&ev2,    cudaEventDisableTiming);
        cudaEventCreateWithFlags(&ev3,    cudaEventDisableTiming);
        size_t smem0 = (128*65 + 64*128) * sizeof(float);   // 66 KB
        cudaFuncSetAttribute(k_gemm, cudaFuncAttributeMaxDynamicSharedMemorySize, (int)smem0);
        init_done = true;
    }

    int tpb = 256;
    int nb  = (n + tpb - 1) / tpb;
    size_t smem = (128*65 + 64*128) * sizeof(float);

    // fork
    cudaEventRecord(evRoot, 0);
    cudaStreamWaitEvent(s2, evRoot, 0);
    cudaStreamWaitEvent(s3, evRoot, 0);

    // ---- branch s2: GEMM + column stats ----
    cudaMemsetAsync(pStats, 0, 2*COUT*4, s2);
    k_gemm<<<(n + 127)/128, 256, smem, s2>>>(feat, Wm, n);
    cudaEventRecord(ev2, s2);

    // ---- branch s3: output padding ----
    cudaMemsetAsync(oCoord, 0, (size_t)3*n*4,    s3);
    cudaMemsetAsync(oFeat,  0, (size_t)n*COUT*4, s3);
    cudaMemsetAsync(oCnt,   0, (size_t)n*4,      s3);
    k_fillbatch<<<nb, tpb, 0, s3>>>(oBatch, n);
    cudaEventRecord(ev3, s3);

    // ---- main branch: voxel chain ----
    cudaMemsetAsync(pBits,  0,    (size_t)NWORDS*4);
    cudaMemsetAsync(pStart, 0xFF, NSCN*3*4);
    cudaMemsetAsync(pCcnt,  0,    (size_t)CSL*4);
    k_scene_min<<<512, tpb>>>(coord, offset, n);
    k_vkey<<<nb, tpb>>>(coord, offset, n);
    b_scan<<<1, 256>>>();
    k_assign<<<nb, tpb>>>(oClus, n);
    c_scan<<<1, 256>>>();
    k_fill<<<nb, tpb>>>(n);

    // join: gather needs GEMM output, colstats, and padded outputs
    cudaStreamWaitEvent(0, ev2, 0);
    cudaStreamWaitEvent(0, ev3, 0);
    k_gather<<<2048, COUT>>>(coord, offset, gamma, beta,
                             oCoord, oFeat, oCnt, oBatch, n);
}

// round 13
// speedup vs baseline: 1.5724x; 1.5724x over previous
#include <cuda_runtime.h>
#include <cuda_bf16.h>
#include <math.h>
#include <stdint.h>

// Problem constants (GridPool, N=300000, B=4, C_IN=64, C_OUT=128, GRID=0.5)
#define NPTS   300000
#define CIN    64
#define COUT   128
#define NSCN   4
#define MDIM2  32
#define KSIZE  (NSCN*MDIM2*MDIM2*MDIM2)   // 131,072 keys
#define NWORDS (KSIZE/32)                 // 4,096 bitmap words
#define CSL    32768                      // cluster-rank bound: 4*20^3 < 32768
#define GRIDSZ 0.5f
#define BN_EPS 1e-5f

#define AST 72                      // smem row stride in bf16 (144B; 4-bank shift/row)
#define TILE_BF (128*AST)           // 9216 bf16 = 18432 B per tile
#define GEMM_SMEM (4*TILE_BF*2)     // 73728 B (4 tiles); epilogue red aliases

// ---------------- scratch (device globals) -----------------------------------
__device__ float    g_x[(size_t)NPTS*COUT];     // fc output (fp32)
__device__ int      g_vkey[NPTS];
__device__ int      g_cluster[NPTS];
__device__ unsigned g_bits[NWORDS];             // presence bitmap (1 bit/key)
__device__ int      g_wordrank[NWORDS];         // exclusive popcount scan per word
__device__ int      g_ncl;                      // total cluster count
__device__ unsigned g_startbits[NSCN*3];        // per-scene min coord (float bits)
__device__ float    g_colstats[2*COUT];         // [0:128) sum, [128:256) sumsq
__device__ int      g_ccnt[CSL];                // per-cluster point count
__device__ int      g_cstart[CSL];              // per-cluster start (end after fill)
__device__ int      g_plist[NPTS];              // point indices grouped by cluster

// ---------------- mma helpers -------------------------------------------------
__device__ __forceinline__ uint32_t smem_u32(const void* p) {
    uint32_t a;
    asm("{ .reg .u64 t; cvta.to.shared.u64 t, %1; cvt.u32.u64 %0, t; }"
        : "=r"(a) : "l"(p));
    return a;
}

#define LDSM4(R, addr) \
    asm volatile("ldmatrix.sync.aligned.m8n8.x4.shared.b16 {%0,%1,%2,%3}, [%4];" \
        : "=r"((R)[0]), "=r"((R)[1]), "=r"((R)[2]), "=r"((R)[3]) : "r"(addr))

#define MMA_BF16(C, A, B0, B1) \
    asm volatile("mma.sync.aligned.m16n8k16.row.col.f32.bf16.bf16.f32 " \
        "{%0,%1,%2,%3},{%4,%5,%6,%7},{%8,%9},{%0,%1,%2,%3};" \
        : "+f"((C)[0]), "+f"((C)[1]), "+f"((C)[2]), "+f"((C)[3]) \
        : "r"((A)[0]), "r"((A)[1]), "r"((A)[2]), "r"((A)[3]), "r"(B0), "r"(B1))

// ---------------- helpers ----------------------------------------------------
__device__ __forceinline__ int point_batch(int i, int o0, int o1, int o2) {
    return (i >= o0) + (i >= o1) + (i >= o2);
}

__device__ unsigned block_exscan256u(unsigned v) {   // 256 threads
    unsigned lane = threadIdx.x & 31, wid = threadIdx.x >> 5;
    unsigned x = v;
    #pragma unroll
    for (int o = 1; o < 32; o <<= 1) {
        unsigned y = __shfl_up_sync(0xffffffffu, x, o);
        if (lane >= o) x += y;
    }
    __shared__ unsigned ws[8];
    if (lane == 31) ws[wid] = x;
    __syncthreads();
    unsigned woff = 0;
    #pragma unroll
    for (unsigned w = 0; w < 8; w++) woff += (w < wid) ? ws[w] : 0u;
    __syncthreads();
    return woff + x - v;
}

// ---------------- kernels ----------------------------------------------------
__global__ void k_scene_min(const float* __restrict__ coord,
                            const int* __restrict__ offset, int n) {
    __shared__ unsigned smin[NSCN*3];
    if (threadIdx.x < NSCN*3) smin[threadIdx.x] = 0xFFFFFFFFu;
    __syncthreads();
    int o0 = offset[0], o1 = offset[1], o2 = offset[2];
    for (int i = blockIdx.x*blockDim.x + threadIdx.x; i < n; i += gridDim.x*blockDim.x) {
        int b = point_batch(i, o0, o1, o2);
        #pragma unroll
        for (int d = 0; d < 3; d++)
            atomicMin(&smin[b*3+d], __float_as_uint(coord[(size_t)i*3+d]));
    }
    __syncthreads();
    if (threadIdx.x < NSCN*3) atomicMin(&g_startbits[threadIdx.x], smin[threadIdx.x]);
}

__global__ void k_vkey(const float* __restrict__ coord,
                       const int* __restrict__ offset, int n) {
    int i = blockIdx.x*blockDim.x + threadIdx.x;
    if (i >= n) return;
    int o0 = offset[0], o1 = offset[1], o2 = offset[2];
    int b = point_batch(i, o0, o1, o2);
    float sx = __uint_as_float(g_startbits[b*3+0]);
    float sy = __uint_as_float(g_startbits[b*3+1]);
    float sz = __uint_as_float(g_startbits[b*3+2]);
    int vx = (int)floorf((coord[(size_t)i*3+0] - sx) / GRIDSZ);
    int vy = (int)floorf((coord[(size_t)i*3+1] - sy) / GRIDSZ);
    int vz = (int)floorf((coord[(size_t)i*3+2] - sz) / GRIDSZ);
    int key = ((b*MDIM2 + vx)*MDIM2 + vy)*MDIM2 + vz;
    g_vkey[i] = key;
    atomicOr(&g_bits[key >> 5], 1u << (key & 31));
}

__global__ void __launch_bounds__(256) b_scan() {
    int base = threadIdx.x*16;
    unsigned pc[16];
    const uint4* p = (const uint4*)&g_bits[base];
    unsigned s = 0;
    #pragma unroll
    for (int j = 0; j < 4; j++) {
        uint4 q = p[j];
        pc[j*4+0]=__popc(q.x); pc[j*4+1]=__popc(q.y);
        pc[j*4+2]=__popc(q.z); pc[j*4+3]=__popc(q.w);
        s += pc[j*4+0]+pc[j*4+1]+pc[j*4+2]+pc[j*4+3];
    }
    unsigned run = block_exscan256u(s);
    #pragma unroll
    for (int j = 0; j < 16; j++) { g_wordrank[base+j] = (int)run; run += pc[j]; }
    if (threadIdx.x == 255) g_ncl = (int)run;
}

// bf16 hi/lo split tensor-core GEMM via mma.sync: x[n,128] = feat[n,64] @ W[64,128]
// D = Ah*Bh + Al*Bh + Ah*Bl (fp32 accum). Tile 128x128xK64, 8 warps (4M x 2N).
__global__ void __launch_bounds__(256)
k_gemm(const float* __restrict__ feat, const float* __restrict__ Wm, int n) {
    extern __shared__ __align__(128) unsigned char dsm[];
    __nv_bfloat16* Ah = (__nv_bfloat16*)dsm;              // [128][AST]
    __nv_bfloat16* Al = Ah + TILE_BF;
    __nv_bfloat16* Bh = Al + TILE_BF;                     // [128 n][AST k]
    __nv_bfloat16* Bl = Bh + TILE_BF;
    float* red = (float*)dsm;                             // epilogue alias: [2][128][33]

    int tid = threadIdx.x, lane = tid & 31, wid = tid >> 5;
    int row0 = blockIdx.x*128;

    // A: feat rows (zero-padded), bf16 hi/lo
    for (int idx = tid; idx < 128*32; idx += 256) {
        int r = idx >> 5, cp = idx & 31;
        int gr = row0 + r;
        float2 v = (gr < n) ? ((const float2*)feat)[(size_t)gr*32 + cp]
                            : make_float2(0.f, 0.f);
        __nv_bfloat16 h0 = __float2bfloat16(v.x);
        __nv_bfloat16 h1 = __float2bfloat16(v.y);
        __nv_bfloat16 l0 = __float2bfloat16(v.x - __bfloat162float(h0));
        __nv_bfloat16 l1 = __float2bfloat16(v.y - __bfloat162float(h1));
        __nv_bfloat162 ph; ph.x = h0; ph.y = h1;
        __nv_bfloat162 pl; pl.x = l0; pl.y = l1;
        *(__nv_bfloat162*)&Ah[r*AST + 2*cp] = ph;
        *(__nv_bfloat162*)&Al[r*AST + 2*cp] = pl;
    }
    // B: transpose W[k][n] -> Bs[n][k], bf16 hi/lo
    for (int idx = tid; idx < CIN*COUT; idx += 256) {
        int k = idx >> 7, nn = idx & 127;
        float w = Wm[idx];
        __nv_bfloat16 h = __float2bfloat16(w);
        __nv_bfloat16 l = __float2bfloat16(w - __bfloat162float(h));
        Bh[nn*AST + k] = h;
        Bl[nn*AST + k] = l;
    }
    __syncthreads();

    int wm = wid >> 1, wn = wid & 1;
    int lr = lane & 15, lk = lane >> 4;
    uint32_t aAh = smem_u32(Ah), aAl = smem_u32(Al);
    uint32_t aBh = smem_u32(Bh), aBl = smem_u32(Bl);

    float acc[2][8][4];
    #pragma unroll
    for (int mt = 0; mt < 2; mt++)
        #pragma unroll
        for (int nt = 0; nt < 8; nt++)
            #pragma unroll
            for (int q = 0; q < 4; q++) acc[mt][nt][q] = 0.f;

    #pragma unroll
    for (int ks = 0; ks < 4; ks++) {
        int k0 = ks*16;
        uint32_t ah[2][4], al[2][4], bh[4][4], bl[4][4];
        #pragma unroll
        for (int mt = 0; mt < 2; mt++) {
            uint32_t off = (uint32_t)(((wm*32 + mt*16 + lr)*AST + k0 + lk*8) * 2);
            LDSM4(ah[mt], aAh + off);
            LDSM4(al[mt], aAl + off);
        }
        #pragma unroll
        for (int g = 0; g < 4; g++) {
            uint32_t off = (uint32_t)(((wn*64 + g*16 + lr)*AST + k0 + lk*8) * 2);
            LDSM4(bh[g], aBh + off);
            LDSM4(bl[g], aBl + off);
        }
        #pragma unroll
        for (int mt = 0; mt < 2; mt++)
            #pragma unroll
            for (int g = 0; g < 4; g++)
                #pragma unroll
                for (int h = 0; h < 2; h++) {
                    int nt = g*2 + h;
                    MMA_BF16(acc[mt][nt], ah[mt], bh[g][h], bh[g][h+2]);
                    MMA_BF16(acc[mt][nt], al[mt], bh[g][h], bh[g][h+2]);
                    MMA_BF16(acc[mt][nt], ah[mt], bl[g][h], bl[g][h+2]);
                }
    }

    // store x
    int r4 = lane >> 2, c2 = lane & 3;
    #pragma unroll
    for (int mt = 0; mt < 2; mt++) {
        int gr0 = row0 + wm*32 + mt*16 + r4;
        #pragma unroll
        for (int nt = 0; nt < 8; nt++) {
            int col = wn*64 + nt*8 + 2*c2;
            if (gr0 < n)
                *(float2*)&g_x[(size_t)gr0*COUT + col] = make_float2(acc[mt][nt][0], acc[mt][nt][1]);
            if (gr0 + 8 < n)
                *(float2*)&g_x[(size_t)(gr0+8)*COUT + col] = make_float2(acc[mt][nt][2], acc[mt][nt][3]);
        }
    }

    // fused column stats (padded rows contribute 0)
    __syncthreads();                 // tiles dead -> alias smem as red
    int grp = wm*8 + r4;             // 32 groups per column
    #pragma unroll
    for (int nt = 0; nt < 8; nt++) {
        int col = wn*64 + nt*8 + 2*c2;
        float s0 = 0.f, s1 = 0.f, q0 = 0.f, q1 = 0.f;
        #pragma unroll
        for (int mt = 0; mt < 2; mt++) {
            float c0 = acc[mt][nt][0], c1 = acc[mt][nt][1];
            float c2f = acc[mt][nt][2], c3 = acc[mt][nt][3];
            s0 += c0 + c2f;  s1 += c1 + c3;
            q0 += c0*c0 + c2f*c2f;  q1 += c1*c1 + c3*c3;
        }
        red[col*33 + grp]              = s0;
        red[(col+1)*33 + grp]          = s1;
        red[(COUT + col)*33 + grp]     = q0;
        red[(COUT + col+1)*33 + grp]   = q1;
    }
    __syncthreads();
    {
        int c = tid;                 // 256 threads: 0-127 sums, 128-255 sumsq
        float s = 0.f;
        #pragma unroll 4
        for (int g = 0; g < 32; g++) s += red[c*33 + g];
        atomicAdd(&g_colstats[c], s);
    }
}

__global__ void k_assign(float* __restrict__ oClus, int n) {
    int i = blockIdx.x*blockDim.x + threadIdx.x;
    if (i >= n) return;
    int key = g_vkey[i];
    unsigned w = g_bits[key >> 5];
    int c = g_wordrank[key >> 5] + __popc(w & ((1u << (key & 31)) - 1u));
    g_cluster[i] = c;
    oClus[i] = (float)c;
    atomicAdd(&g_ccnt[c], 1);
}

__global__ void __launch_bounds__(256) c_scan() {
    int base = threadIdx.x*128;
    const int4* p = (const int4*)&g_ccnt[base];
    int s = 0;
    #pragma unroll
    for (int j = 0; j < 32; j++) { int4 v = p[j]; s += v.x+v.y+v.z+v.w; }
    int run = (int)block_exscan256u((unsigned)s);
    int4* q = (int4*)&g_cstart[base];
    #pragma unroll
    for (int j = 0; j < 32; j++) {
        int4 v = p[j];
        int4 o;
        o.x = run;  run += v.x;
        o.y = run;  run += v.y;
        o.z = run;  run += v.z;
        o.w = run;  run += v.w;
        q[j] = o;
    }
}

__global__ void k_fill(int n) {
    int i = blockIdx.x*blockDim.x + threadIdx.x;
    if (i >= n) return;
    int c = g_cluster[i];
    int slot = atomicAdd(&g_cstart[c], 1);
    g_plist[slot] = i;
}

__global__ void k_fillbatch(float* __restrict__ oBatch, int n) {
    int i = blockIdx.x*blockDim.x + threadIdx.x;
    if (i < n) oBatch[i] = 2147483648.0f;   // (float)INT32_MAX
}

__global__ void __launch_bounds__(128)
k_gather(const float* __restrict__ coord,
         const int* __restrict__ offset,
         const float* __restrict__ gamma,
         const float* __restrict__ beta,
         float* __restrict__ oCoord, float* __restrict__ oFeat,
         float* __restrict__ oCnt, float* __restrict__ oBatch, int n) {
    int j = threadIdx.x;            // 128 threads
    int ncl = g_ncl;
    float inv_n = 1.f / (float)n;
    float mean = g_colstats[j] * inv_n;
    float var  = g_colstats[COUT + j] * inv_n - mean*mean;
    float a    = gamma[j] * rsqrtf(var + BN_EPS);
    float bb   = beta[j] - a*mean;
    int o0 = offset[0], o1 = offset[1], o2 = offset[2];

    for (int c = blockIdx.x; c < ncl; c += gridDim.x) {
        int cnt = g_ccnt[c];
        int end = g_cstart[c];
        int start = end - cnt;
        float m0 = 0.f, m1 = 0.f;       // ReLU identity
        int p = 0;
        for (; p + 1 < cnt; p += 2) {
            int i0 = g_plist[start+p];
            int i1 = g_plist[start+p+1];
            float y0 = a * g_x[(size_t)i0*COUT + j] + bb;
            float y1 = a * g_x[(size_t)i1*COUT + j] + bb;
            m0 = fmaxf(m0, y0);
            m1 = fmaxf(m1, y1);
        }
        if (p < cnt) {
            int i0 = g_plist[start+p];
            m0 = fmaxf(m0, a * g_x[(size_t)i0*COUT + j] + bb);
        }
        oFeat[(size_t)c*COUT + j] = fmaxf(m0, m1);
        if (j < 3) {
            float s = 0.f;
            for (int q = 0; q < cnt; q++) {
                int i = g_plist[start+q];
                s += coord[(size_t)i*3 + j];
            }
            oCoord[(size_t)c*3 + j] = s / (float)cnt;
        }
        if (j == 0) {
            oCnt[c] = (float)cnt;
            int i0 = g_plist[start];
            oBatch[c] = (float)point_batch(i0, o0, o1, o2);
        }
    }
}

// ---------------- launch -----------------------------------------------------
extern "C" void kernel_launch(void* const* d_in, const int* in_sizes, int n_in,
                              void* d_out, int out_size) {
    const float* coord  = (const float*)d_in[0];
    const float* feat   = (const float*)d_in[1];
    const int*   offset = (const int*)  d_in[2];
    const float* Wm     = (const float*)d_in[3];
    const float* gamma  = (const float*)d_in[4];
    const float* beta   = (const float*)d_in[5];
    const int n = in_sizes[0] / 3;

    float* out    = (float*)d_out;
    float* oCoord = out;
    float* oFeat  = out + (size_t)3*n;
    float* oClus  = out + (size_t)131*n;
    float* oCnt   = out + (size_t)132*n;
    float* oBatch = out + (size_t)133*n;

    void *pBits, *pStart, *pStats, *pCcnt;
    cudaGetSymbolAddress(&pBits,  g_bits);
    cudaGetSymbolAddress(&pStart, g_startbits);
    cudaGetSymbolAddress(&pStats, g_colstats);
    cudaGetSymbolAddress(&pCcnt,  g_ccnt);

    static cudaStream_t s2 = nullptr, s3 = nullptr;
    static cudaEvent_t evRoot = nullptr, ev2 = nullptr, ev3 = nullptr;
    static bool init_done = false;
    if (!init_done) {
        cudaStreamCreateWithFlags(&s2, cudaStreamNonBlocking);
        cudaStreamCreateWithFlags(&s3, cudaStreamNonBlocking);
        cudaEventCreateWithFlags(&evRoot, cudaEventDisableTiming);
        cudaEventCreateWithFlags(&ev2,    cudaEventDisableTiming);
        cudaEventCreateWithFlags(&ev3,    cudaEventDisableTiming);
        cudaFuncSetAttribute(k_gemm, cudaFuncAttributeMaxDynamicSharedMemorySize, GEMM_SMEM);
        init_done = true;
    }

    int tpb = 256;
    int nb  = (n + tpb - 1) / tpb;

    // fork
    cudaEventRecord(evRoot, 0);
    cudaStreamWaitEvent(s2, evRoot, 0);
    cudaStreamWaitEvent(s3, evRoot, 0);

    // ---- branch s2: GEMM + column stats ----
    cudaMemsetAsync(pStats, 0, 2*COUT*4, s2);
    k_gemm<<<(n + 127)/128, 256, GEMM_SMEM, s2>>>(feat, Wm, n);
    cudaEventRecord(ev2, s2);

    // ---- branch s3: output padding ----
    cudaMemsetAsync(oCoord, 0, (size_t)3*n*4,    s3);
    cudaMemsetAsync(oFeat,  0, (size_t)n*COUT*4, s3);
    cudaMemsetAsync(oCnt,   0, (size_t)n*4,      s3);
    k_fillbatch<<<nb, tpb, 0, s3>>>(oBatch, n);
    cudaEventRecord(ev3, s3);

    // ---- main branch: voxel chain ----
    cudaMemsetAsync(pBits,  0,    (size_t)NWORDS*4);
    cudaMemsetAsync(pStart, 0xFF, NSCN*3*4);
    cudaMemsetAsync(pCcnt,  0,    (size_t)CSL*4);
    k_scene_min<<<512, tpb>>>(coord, offset, n);
    k_vkey<<<nb, tpb>>>(coord, offset, n);
    b_scan<<<1, 256>>>();
    k_assign<<<nb, tpb>>>(oClus, n);
    c_scan<<<1, 256>>>();
    k_fill<<<nb, tpb>>>(n);

    // join: gather needs GEMM output, colstats, and padded outputs
    cudaStreamWaitEvent(0, ev2, 0);
    cudaStreamWaitEvent(0, ev3, 0);
    k_gather<<<2048, COUT>>>(coord, offset, gamma, beta,
                             oCoord, oFeat, oCnt, oBatch, n);
}